// round 12
// baseline (speedup 1.0000x reference)
#include <cuda_runtime.h>
#include <cuda_fp16.h>

#define HID   64
#define CDIM  256     // HEADS*HID
#define NMAX  65536
#define EMAX  524288

// ---------------- scratch (static device arrays; no allocation) ----------------
__device__ float    g_wc [3 * HID];       // combined embedding weight [3][64]
__device__ float    g_bc [HID];           // combined embedding bias
__device__ float    g_WL3[3 * CDIM];      // Wc @ gat_wl  [3][256]
__device__ float    g_bL [CDIM];
__device__ float    g_WR3[3 * CDIM];      // Wc @ gat_wr  [3][256]
__device__ float    g_bR [CDIM];
__device__ unsigned g_pk [NMAX];          // packed per-node: prog(float, low 2 bits = combo)
__device__ float    g_y [NMAX * HID];     // post-LN features
__device__ int      g_deg [NMAX];         // zeroed by scan_scatter each replay
__device__ int      g_off [NMAX + 1];
__device__ int      g_cur [NMAX];
__device__ int      g_bsum[64];
__device__ int      g_bpre[64];
__device__ int      g_cnt1 = 0;
__device__ int      g_cnt2 = 0;
__device__ int      g_cnt3 = 0;
__device__ volatile int g_flag1 = 0;
__device__ volatile int g_flag2 = 0;
__device__ int      g_csr [EMAX];         // src per dst-sorted edge

// ---------------- helpers ----------------
__device__ __forceinline__ float decode_t(const void* p) {
    int iv = *(const int*)p;
    if (iv > -16777216 && iv < 16777216) return (float)iv;   // int32 / int64 low word
    return __int_as_float(iv);                               // float32
}

__device__ __forceinline__ __half2 shfl_xor_h2(__half2 v, int m) {
    unsigned u = *(unsigned*)&v;
    u = __shfl_xor_sync(0xffffffffu, u, m);
    return *(__half2*)&u;
}

// ---------------- K0: prep weights (block 0) + packed node features + histogram --------
__global__ __launch_bounds__(256) void prep_kernel(
        const float* __restrict__ arr, const float* __restrict__ dep,
        const float* __restrict__ hard, const void* __restrict__ tptr,
        const float* __restrict__ w1, const float* __restrict__ b1,
        const float* __restrict__ w2, const float* __restrict__ b2,
        const float* __restrict__ wl, const float* __restrict__ wr,
        const int* __restrict__ ei, int n, int E) {
    int t = threadIdx.x;   // 256 threads
    if (blockIdx.x == 0) {
        __shared__ float sWc[3 * HID];
        __shared__ float sbc[HID];
        if (t < HID) {
            float c0 = 0.f, c1 = 0.f, c2 = 0.f, cb = 0.f;
            for (int k = 0; k < HID; k++) {
                float wkj = w2[k * HID + t];
                c0 += w1[k] * wkj;
                c1 += w1[HID + k] * wkj;
                c2 += w1[2 * HID + k] * wkj;
                cb += b1[k] * wkj;
            }
            sWc[t] = c0; sWc[HID + t] = c1; sWc[2 * HID + t] = c2; sbc[t] = cb + b2[t];
            g_wc[t] = c0; g_wc[HID + t] = c1; g_wc[2 * HID + t] = c2; g_bc[t] = sbc[t];
        }
        __syncthreads();
        float l0 = 0.f, l1 = 0.f, l2 = 0.f, lb = 0.f;
        float r0 = 0.f, r1 = 0.f, r2 = 0.f, rb = 0.f;
#pragma unroll 8
        for (int j = 0; j < HID; j++) {
            float wlv = wl[j * CDIM + t], wrv = wr[j * CDIM + t];
            float wc0 = sWc[j], wc1 = sWc[HID + j], wc2 = sWc[2 * HID + j], bcv = sbc[j];
            l0 += wc0 * wlv; l1 += wc1 * wlv; l2 += wc2 * wlv; lb += bcv * wlv;
            r0 += wc0 * wrv; r1 += wc1 * wrv; r2 += wc2 * wrv; rb += bcv * wrv;
        }
        g_WL3[t] = l0; g_WL3[CDIM + t] = l1; g_WL3[2 * CDIM + t] = l2; g_bL[t] = lb;
        g_WR3[t] = r0; g_WR3[CDIM + t] = r1; g_WR3[2 * CDIM + t] = r2; g_bR[t] = rb;
    }

    float tv = decode_t(tptr);
    for (int node = blockIdx.x * 256 + t; node < n; node += gridDim.x * 256) {
        float a = arr[node], d = dep[node], h = hard[node];
        float prog = (tv - a) / fmaxf(d - a, 1.0f);
        unsigned c = (h != 0.f ? 1u : 0u) | (((d - tv) <= 1.0f) ? 2u : 0u);
        g_pk[node] = (__float_as_uint(prog) & ~3u) | c;
    }
    // destination histogram (g_deg zeroed by previous replay's scan_scatter)
    for (int e = blockIdx.x * 256 + t; e < E; e += gridDim.x * 256)
        atomicAdd(&g_deg[ei[E + e]], 1);
}

// ---------------- K1: fused scan + scatter (warp-shuffle block scan) ----------------
__global__ __launch_bounds__(1024) void scan_scatter_kernel(const int* __restrict__ ei,
                                                            int n, int E) {
    __shared__ int swp[32];   // per-warp totals / exclusive prefixes
    int t = threadIdx.x;
    int b = blockIdx.x;
    int nb = gridDim.x;
    int wid = t >> 5;
    int l = t & 31;
    int idx = b * 1024 + t;
    int v = (idx < n) ? g_deg[idx] : 0;
    if (idx < n) g_deg[idx] = 0;          // reset for next replay's histogram

    // warp inclusive scan
    int run = v;
#pragma unroll
    for (int ofs = 1; ofs < 32; ofs <<= 1) {
        int u = __shfl_up_sync(0xffffffffu, run, ofs);
        if (l >= ofs) run += u;
    }
    if (l == 31) swp[wid] = run;
    __syncthreads();
    if (wid == 0) {
        int wv = swp[l];
        int wrun = wv;
#pragma unroll
        for (int ofs = 1; ofs < 32; ofs <<= 1) {
            int u = __shfl_up_sync(0xffffffffu, wrun, ofs);
            if (l >= ofs) wrun += u;
        }
        swp[l] = wrun - wv;   // exclusive warp prefix
        if (l == 31) {
            g_bsum[b] = wrun;  // block total
            __threadfence();
            int arrived = atomicAdd(&g_cnt1, 1);
            if (arrived == nb - 1) {
                int acc = 0;
                for (int k = 0; k < nb; k++) { g_bpre[k] = acc; acc += g_bsum[k]; }
                g_off[n] = acc;
                __threadfence();
                g_flag1 = 1;
            }
        }
    }
    if (t == 0) { while (g_flag1 == 0) { __nanosleep(20); } }
    __syncthreads();
    __threadfence();
    int local_excl = run - v + swp[wid];
    int bp = g_bpre[b];
    if (idx < n) {
        int o = local_excl + bp;
        g_off[idx] = o;
        g_cur[idx] = o;
    }
    __syncthreads();
    // global sync #2: all g_cur written before any scatter
    if (t == 0) {
        __threadfence();
        int done = atomicAdd(&g_cnt2, 1);
        if (done == nb - 1) { __threadfence(); g_flag2 = 1; }
        while (g_flag2 == 0) { __nanosleep(20); }
    }
    __syncthreads();
    __threadfence();
    int nthreads = nb * 1024;
    for (int e = b * 1024 + t; e < E; e += nthreads) {
        int src = ei[e];
        int dst = ei[E + e];
        int p = atomicAdd(&g_cur[dst], 1);
        g_csr[p] = src;
    }
    // reset barrier state for the next graph replay
    __syncthreads();
    if (t == 0) {
        __threadfence();
        int done = atomicAdd(&g_cnt3, 1);
        if (done == nb - 1) {
            g_cnt1 = 0; g_cnt2 = 0; g_cnt3 = 0; g_flag1 = 0; g_flag2 = 0;
        }
    }
}

// ---------------- K2: GAT via affine decomposition (no row gathers) + LN ----------------
__global__ __launch_bounds__(256) void gat_kernel(const float* __restrict__ att,
                                                  const float* __restrict__ gbias,
                                                  const float* __restrict__ arr,
                                                  const float* __restrict__ dep,
                                                  const float* __restrict__ hard,
                                                  const void* __restrict__ tptr, int n) {
    int warp = (blockIdx.x * blockDim.x + threadIdx.x) >> 5;
    if (warp >= n) return;
    int l = threadIdx.x & 31;
    int i = warp;
    int base = l * 8;          // lane's 8 slots in the 256-wide [head][dim] vector
    int dimb = (l & 7) * 8;    // lane's 8 dims in 0..63

    float tv = decode_t(tptr);
    float a = arr[i], d = dep[i], h = hard[i];
    float prog = (tv - a) / fmaxf(d - a, 1.0f);
    float atl  = ((d - tv) <= 1.0f) ? 1.0f : 0.0f;

    const __half2 c02 = __floats2half2_rn(0.2f, 0.2f);
    const __half2 hz  = __floats2half2_rn(0.f, 0.f);

    __half2 att2[4];
#pragma unroll
    for (int c = 0; c < 4; c++)
        att2[c] = __floats2half2_rn(att[base + 2 * c], att[base + 2 * c + 1]);

    // xr for this dst (fp32), folded into the 4 combo tables Tc = U_c + xr
    float xr8[8];
#pragma unroll
    for (int u = 0; u < 8; u++)
        xr8[u] = prog * g_WR3[base + u] + h * g_WR3[CDIM + base + u]
               + atl * g_WR3[2 * CDIM + base + u] + g_bR[base + u];

    __half2 Tc[4][4];
#pragma unroll
    for (int c = 0; c < 4; c++) {
        float hc = (float)(c & 1), ac = (float)(c >> 1);
        float tf[8];
#pragma unroll
        for (int u = 0; u < 8; u++)
            tf[u] = hc * g_WL3[CDIM + base + u] + ac * g_WL3[2 * CDIM + base + u]
                  + g_bL[base + u] + xr8[u];
#pragma unroll
        for (int cc = 0; cc < 4; cc++)
            Tc[c][cc] = __floats2half2_rn(tf[2 * cc], tf[2 * cc + 1]);
    }
    __half2 WL0h[4];
#pragma unroll
    for (int cc = 0; cc < 4; cc++)
        WL0h[cc] = __floats2half2_rn(g_WL3[base + 2 * cc], g_WL3[base + 2 * cc + 1]);

    // per-edge score from the packed word (prog float with combo in 2 LSBs)
    auto score = [&](unsigned w) -> __half2 {
        float progs = __uint_as_float(w & ~3u);
        int c = (int)(w & 3u);
        __half2 ph = __float2half2_rn(progs);
        __half2 q = hz;
#pragma unroll
        for (int cc = 0; cc < 4; cc++) {
            __half2 t01 = (c & 1) ? Tc[1][cc] : Tc[0][cc];
            __half2 t23 = (c & 1) ? Tc[3][cc] : Tc[2][cc];
            __half2 tt  = (c & 2) ? t23 : t01;
            __half2 v = __hfma2(ph, WL0h[cc], tt);
            v = __hmax2(v, __hmul2(v, c02));
            q = __hfma2(v, att2[cc], q);
        }
        return q;
    };

    // self-loop: its score p is the softmax shift reference (weight exactly 1)
    unsigned wi = g_pk[i];
    float p;
    {
        __half2 qh = score(wi);
        qh = __hadd2(qh, shfl_xor_h2(qh, 1));
        qh = __hadd2(qh, shfl_xor_h2(qh, 2));
        qh = __hadd2(qh, shfl_xor_h2(qh, 4));
        p = __low2float(qh) + __high2float(qh);
    }
    float s  = 1.0f;          // total softmax weight (self included)
    float S1 = prog;          // weighted sum of src prog
    float Hs = h;             // weighted sum of src is_hard bit
    float As = atl;           // weighted sum of src about_to_leave bit

    int e0i = g_off[i], e1i = g_off[i + 1];
    int j = e0i;
    for (; j + 3 < e1i; j += 4) {
        int s0 = g_csr[j], s1 = g_csr[j + 1], s2 = g_csr[j + 2], s3 = g_csr[j + 3];
        unsigned w0 = g_pk[s0], w1 = g_pk[s1], w2 = g_pk[s2], w3 = g_pk[s3];
        __half2 q0 = score(w0);
        __half2 q1 = score(w1);
        __half2 q2 = score(w2);
        __half2 q3 = score(w3);
        // pack 2 edges per half2 word, reduce across the 8-lane head group
        __half2 A = __halves2half2(__hadd(__low2half(q0), __high2half(q0)),
                                   __hadd(__low2half(q1), __high2half(q1)));
        __half2 B = __halves2half2(__hadd(__low2half(q2), __high2half(q2)),
                                   __hadd(__low2half(q3), __high2half(q3)));
        A = __hadd2(A, shfl_xor_h2(A, 1));
        B = __hadd2(B, shfl_xor_h2(B, 1));
        A = __hadd2(A, shfl_xor_h2(A, 2));
        B = __hadd2(B, shfl_xor_h2(B, 2));
        A = __hadd2(A, shfl_xor_h2(A, 4));
        B = __hadd2(B, shfl_xor_h2(B, 4));

        float e0 = __expf(__low2float(A) - p);
        float e1 = __expf(__high2float(A) - p);
        float e2 = __expf(__low2float(B) - p);
        float e3 = __expf(__high2float(B) - p);
        s += e0 + e1 + e2 + e3;
        S1 += e0 * __uint_as_float(w0 & ~3u) + e1 * __uint_as_float(w1 & ~3u)
            + e2 * __uint_as_float(w2 & ~3u) + e3 * __uint_as_float(w3 & ~3u);
        Hs += e0 * (float)(w0 & 1u) + e1 * (float)(w1 & 1u)
            + e2 * (float)(w2 & 1u) + e3 * (float)(w3 & 1u);
        As += e0 * (float)((w0 >> 1) & 1u) + e1 * (float)((w1 >> 1) & 1u)
            + e2 * (float)((w2 >> 1) & 1u) + e3 * (float)((w3 >> 1) & 1u);
    }
    for (; j < e1i; j++) {
        unsigned w = g_pk[g_csr[j]];
        __half2 qh = score(w);
        qh = __hadd2(qh, shfl_xor_h2(qh, 1));
        qh = __hadd2(qh, shfl_xor_h2(qh, 2));
        qh = __hadd2(qh, shfl_xor_h2(qh, 4));
        float q = __low2float(qh) + __high2float(qh);
        float wv = __expf(q - p);
        s += wv;
        S1 += wv * __uint_as_float(w & ~3u);
        Hs += wv * (float)(w & 1u);
        As += wv * (float)((w >> 1) & 1u);
    }

    // exact fp32 aggregation: sum_j w_j * xl[src_j] = S1*WL0 + Hs*WL1 + As*WL2 + s*bL
    float inv = 1.0f / s;
    float acc[8];
#pragma unroll
    for (int u = 0; u < 8; u++)
        acc[u] = (S1 * g_WL3[base + u] + Hs * g_WL3[CDIM + base + u]
                + As * g_WL3[2 * CDIM + base + u] + s * g_bL[base + u]) * inv;

    // sum across the 4 heads (lanes l, l^8, l^16, l^24 hold the same dims)
#pragma unroll
    for (int u = 0; u < 8; u++) {
        float v = acc[u];
        v += __shfl_xor_sync(0xffffffffu, v, 8);
        v += __shfl_xor_sync(0xffffffffu, v, 16);
        acc[u] = v;
    }

    // residual x recomputed from features + LN
    float xv[8];
    float sm = 0.f;
#pragma unroll
    for (int u = 0; u < 8; u++) {
        float x8 = prog * g_wc[dimb + u] + h * g_wc[HID + dimb + u]
                 + atl * g_wc[2 * HID + dimb + u] + g_bc[dimb + u];
        xv[u] = x8 + 0.25f * acc[u] + gbias[dimb + u];
        sm += xv[u];
    }
    sm += __shfl_xor_sync(0xffffffffu, sm, 1);
    sm += __shfl_xor_sync(0xffffffffu, sm, 2);
    sm += __shfl_xor_sync(0xffffffffu, sm, 4);
    float mu = sm * (1.0f / 64.0f);
    float sq = 0.f;
#pragma unroll
    for (int u = 0; u < 8; u++) { float dd = xv[u] - mu; sq += dd * dd; }
    sq += __shfl_xor_sync(0xffffffffu, sq, 1);
    sq += __shfl_xor_sync(0xffffffffu, sq, 2);
    sq += __shfl_xor_sync(0xffffffffu, sq, 4);
    float rs = rsqrtf(sq * (1.0f / 64.0f) + 1e-5f);

    if (l < 8) {
        float o[8];
#pragma unroll
        for (int u = 0; u < 8; u++) o[u] = (xv[u] - mu) * rs;
        *(float4*)&g_y[i * HID + dimb]     = make_float4(o[0], o[1], o[2], o[3]);
        *(float4*)&g_y[i * HID + dimb + 4] = make_float4(o[4], o[5], o[6], o[7]);
    }
}

// ---------------- K3: two residual ReLU FF layers (R10 4x4 config) ----------------
__global__ __launch_bounds__(256) void ff_kernel(const float* __restrict__ w1,
                                                 const float* __restrict__ b1,
                                                 const float* __restrict__ w2,
                                                 const float* __restrict__ b2,
                                                 float* __restrict__ out, int n) {
    __shared__ float ysT[64 * 68];
    __shared__ float ws [64 * 68];
    __shared__ float bsh[2 * 64];
    int tid = threadIdx.x;
    int n0  = blockIdx.x * 64;

#pragma unroll
    for (int i = 0; i < 4; i++) {
        int idx = tid + i * 256;
        int r   = idx >> 4;
        int c4  = (idx & 15) * 4;
        float4 v = make_float4(0.f, 0.f, 0.f, 0.f);
        if (n0 + r < n) v = *(const float4*)&g_y[(n0 + r) * HID + c4];
        ysT[(c4 + 0) * 68 + r] = v.x;
        ysT[(c4 + 1) * 68 + r] = v.y;
        ysT[(c4 + 2) * 68 + r] = v.z;
        ysT[(c4 + 3) * 68 + r] = v.w;
        *(float4*)&ws[r * 68 + c4] = *(const float4*)&w1[r * HID + c4];
    }
    if (tid < 64) { bsh[tid] = b1[tid]; bsh[64 + tid] = b2[tid]; }
    __syncthreads();

    int tn = (tid & 15) * 4;
    int tc = (tid >> 4) * 4;

    float z[4][4];
    {
        float acc[4][4];
#pragma unroll
        for (int aa = 0; aa < 4; aa++)
#pragma unroll
            for (int bb = 0; bb < 4; bb++) acc[aa][bb] = 0.f;
#pragma unroll 16
        for (int k = 0; k < 64; k++) {
            float4 av = *(const float4*)&ysT[k * 68 + tn];
            float4 bv = *(const float4*)&ws [k * 68 + tc];
            float a4[4] = {av.x, av.y, av.z, av.w};
            float b4[4] = {bv.x, bv.y, bv.z, bv.w};
#pragma unroll
            for (int ii = 0; ii < 4; ii++)
#pragma unroll
                for (int jj = 0; jj < 4; jj++) acc[ii][jj] += a4[ii] * b4[jj];
        }
#pragma unroll
        for (int nn = 0; nn < 4; nn++)
#pragma unroll
            for (int cc = 0; cc < 4; cc++) {
                float yv = ysT[(tc + cc) * 68 + tn + nn];
                float r  = acc[nn][cc] + bsh[tc + cc];
                z[nn][cc] = yv + fmaxf(r, 0.f);
            }
    }
    __syncthreads();

#pragma unroll
    for (int cc = 0; cc < 4; cc++)
        *(float4*)&ysT[(tc + cc) * 68 + tn] =
            make_float4(z[0][cc], z[1][cc], z[2][cc], z[3][cc]);
#pragma unroll
    for (int i = 0; i < 4; i++) {
        int idx = tid + i * 256;
        int r   = idx >> 4;
        int c4  = (idx & 15) * 4;
        *(float4*)&ws[r * 68 + c4] = *(const float4*)&w2[r * HID + c4];
    }
    __syncthreads();

    float acc2[4][4];
#pragma unroll
    for (int aa = 0; aa < 4; aa++)
#pragma unroll
        for (int bb = 0; bb < 4; bb++) acc2[aa][bb] = 0.f;
#pragma unroll 16
    for (int k = 0; k < 64; k++) {
        float4 av = *(const float4*)&ysT[k * 68 + tn];
        float4 bv = *(const float4*)&ws [k * 68 + tc];
        float a4[4] = {av.x, av.y, av.z, av.w};
        float b4[4] = {bv.x, bv.y, bv.z, bv.w};
#pragma unroll
        for (int ii = 0; ii < 4; ii++)
#pragma unroll
            for (int jj = 0; jj < 4; jj++) acc2[ii][jj] += a4[ii] * b4[jj];
    }
#pragma unroll
    for (int nn = 0; nn < 4; nn++) {
        int row = n0 + tn + nn;
        if (row < n) {
            float o[4];
#pragma unroll
            for (int cc = 0; cc < 4; cc++) {
                float zv = ysT[(tc + cc) * 68 + tn + nn];
                float r2 = acc2[nn][cc] + bsh[64 + tc + cc];
                o[cc] = zv + fmaxf(r2, 0.f);
            }
            *(float4*)&out[row * HID + tc] = make_float4(o[0], o[1], o[2], o[3]);
        }
    }
}

// ---------------- launch ----------------
extern "C" void kernel_launch(void* const* d_in, const int* in_sizes, int n_in,
                              void* d_out, int out_size) {
    const float* arrivals = (const float*)d_in[0];
    const float* departs  = (const float*)d_in[1];
    const float* hard     = (const float*)d_in[2];
    const float* w_emb1   = (const float*)d_in[3];
    const float* b_emb1   = (const float*)d_in[4];
    const float* w_emb2   = (const float*)d_in[5];
    const float* b_emb2   = (const float*)d_in[6];
    const float* gat_wl   = (const float*)d_in[7];
    const float* gat_wr   = (const float*)d_in[8];
    const float* gat_att  = (const float*)d_in[9];
    const float* gat_bias = (const float*)d_in[10];
    const float* w_ff1    = (const float*)d_in[11];
    const float* b_ff1    = (const float*)d_in[12];
    const float* w_ff2    = (const float*)d_in[13];
    const float* b_ff2    = (const float*)d_in[14];
    const int*   edge     = (const int*)d_in[15];
    const void*  tptr     = d_in[16];

    int n = in_sizes[0];
    int E = in_sizes[15] / 2;

    prep_kernel<<<296, 256>>>(arrivals, departs, hard, tptr,
                              w_emb1, b_emb1, w_emb2, b_emb2,
                              gat_wl, gat_wr, edge, n, E);                          // 0
    int nb = (n + 1023) / 1024;
    scan_scatter_kernel<<<nb, 1024>>>(edge, n, E);                                  // 1
    gat_kernel<<<(n + 7) / 8, 256>>>(gat_att, gat_bias, arrivals, departs, hard,
                                     tptr, n);                                      // 2
    ff_kernel<<<(n + 63) / 64, 256>>>(w_ff1, b_ff1, w_ff2, b_ff2, (float*)d_out, n); // 3
}

// round 13
// speedup vs baseline: 1.3522x; 1.3522x over previous
#include <cuda_runtime.h>
#include <cuda_fp16.h>

#define HID   64
#define CDIM  256     // HEADS*HID
#define NMAX  65536
#define EMAX  524288

// ---------------- scratch (static device arrays; no allocation) ----------------
__device__ float  g_wc [3 * HID];         // combined embedding weight [3][64]
__device__ float  g_bc [HID];             // combined embedding bias
__device__ float  g_WR3[3 * CDIM];        // Wc @ gat_wr  [3][256]
__device__ float  g_bR [CDIM];
__device__ __half g_xlh[NMAX * CDIM];     // x @ gat_wl  in fp16 (gather operand)
__device__ float  g_y [NMAX * HID];       // post-LN features
__device__ int    g_deg [NMAX];           // zeroed by scan_scatter each replay
__device__ int    g_off [NMAX + 1];
__device__ int    g_cur [NMAX];
__device__ int    g_bsum[64];
__device__ int    g_bpre[64];
__device__ int    g_cnt1 = 0;
__device__ int    g_cnt2 = 0;
__device__ int    g_cnt3 = 0;
__device__ volatile int g_flag1 = 0;
__device__ volatile int g_flag2 = 0;
__device__ int    g_csr [EMAX];           // src per dst-sorted edge (16B-aligned base)

// ---------------- helpers ----------------
__device__ __forceinline__ float decode_t(const void* p) {
    int iv = *(const int*)p;
    if (iv > -16777216 && iv < 16777216) return (float)iv;   // int32 / int64 low word
    return __int_as_float(iv);                               // float32
}

__device__ __forceinline__ __half2 shfl_xor_h2(__half2 v, int m) {
    unsigned u = *(unsigned*)&v;
    u = __shfl_xor_sync(0xffffffffu, u, m);
    return *(__half2*)&u;
}

// ---------------- K0: fused prep + xl(fp16) + dst histogram (persistent) ----------------
__global__ __launch_bounds__(256) void xlprep_kernel(
        const float* __restrict__ arr, const float* __restrict__ dep,
        const float* __restrict__ hard, const void* __restrict__ tptr,
        const float* __restrict__ w1, const float* __restrict__ b1,
        const float* __restrict__ w2, const float* __restrict__ b2,
        const float* __restrict__ wl, const float* __restrict__ wr,
        const int* __restrict__ ei, int n, int E) {
    __shared__ float sWc[3 * HID];
    __shared__ float sbc[HID];
    __shared__ float sWL[3 * CDIM];
    __shared__ float sbL[CDIM];
    int t = threadIdx.x;   // 256 threads

    if (t < HID) {
        float c0 = 0.f, c1 = 0.f, c2 = 0.f, cb = 0.f;
        for (int k = 0; k < HID; k++) {
            float wkj = w2[k * HID + t];
            c0 += w1[k] * wkj;
            c1 += w1[HID + k] * wkj;
            c2 += w1[2 * HID + k] * wkj;
            cb += b1[k] * wkj;
        }
        sWc[t] = c0; sWc[HID + t] = c1; sWc[2 * HID + t] = c2; sbc[t] = cb + b2[t];
    }
    __syncthreads();

    {   // WL3 columns (all blocks; needed locally)
        float l0 = 0.f, l1 = 0.f, l2 = 0.f, lb = 0.f;
#pragma unroll 8
        for (int j = 0; j < HID; j++) {
            float wlv = wl[j * CDIM + t];
            l0 += sWc[j] * wlv;
            l1 += sWc[HID + j] * wlv;
            l2 += sWc[2 * HID + j] * wlv;
            lb += sbc[j] * wlv;
        }
        sWL[t] = l0; sWL[CDIM + t] = l1; sWL[2 * CDIM + t] = l2; sbL[t] = lb;
    }
    if (blockIdx.x == 0) {   // WR3 + wc/bc to global (only gat needs them)
        float r0 = 0.f, r1 = 0.f, r2 = 0.f, rb = 0.f;
#pragma unroll 8
        for (int j = 0; j < HID; j++) {
            float wrv = wr[j * CDIM + t];
            r0 += sWc[j] * wrv;
            r1 += sWc[HID + j] * wrv;
            r2 += sWc[2 * HID + j] * wrv;
            rb += sbc[j] * wrv;
        }
        g_WR3[t] = r0; g_WR3[CDIM + t] = r1; g_WR3[2 * CDIM + t] = r2; g_bR[t] = rb;
        if (t < HID) {
            g_wc[t] = sWc[t]; g_wc[HID + t] = sWc[HID + t];
            g_wc[2 * HID + t] = sWc[2 * HID + t]; g_bc[t] = sbc[t];
        }
    }
    __syncthreads();

    float tv = decode_t(tptr);
    int total = n * 32;
    for (int idx = blockIdx.x * 256 + t; idx < total; idx += gridDim.x * 256) {
        int node = idx >> 5;
        int c = (idx & 31) * 8;
        float a = arr[node], d = dep[node], h = hard[node];
        float prog = (tv - a) / fmaxf(d - a, 1.0f);
        float atl  = ((d - tv) <= 1.0f) ? 1.0f : 0.0f;

        float o[8];
#pragma unroll
        for (int u = 0; u < 8; u++)
            o[u] = prog * sWL[c + u] + h * sWL[CDIM + c + u]
                 + atl * sWL[2 * CDIM + c + u] + sbL[c + u];

        uint4 pk;
        ((__half2*)&pk.x)[0] = __floats2half2_rn(o[0], o[1]);
        ((__half2*)&pk.x)[1] = __floats2half2_rn(o[2], o[3]);
        ((__half2*)&pk.z)[0] = __floats2half2_rn(o[4], o[5]);
        ((__half2*)&pk.z)[1] = __floats2half2_rn(o[6], o[7]);
        *(uint4*)&g_xlh[node * CDIM + c] = pk;
    }

    // destination histogram (g_deg zeroed by previous replay's scan_scatter)
    for (int e = blockIdx.x * 256 + t; e < E; e += gridDim.x * 256)
        atomicAdd(&g_deg[ei[E + e]], 1);
}

// ---------------- K1: fused scan + scatter (grid-wide sync via counters) ----------------
__global__ __launch_bounds__(1024) void scan_scatter_kernel(const int* __restrict__ ei,
                                                            int n, int E) {
    __shared__ int swp[32];   // per-warp totals / exclusive prefixes
    int t = threadIdx.x;
    int b = blockIdx.x;
    int nb = gridDim.x;
    int wid = t >> 5;
    int l = t & 31;
    int idx = b * 1024 + t;
    int v = (idx < n) ? g_deg[idx] : 0;
    if (idx < n) g_deg[idx] = 0;          // reset for next replay's histogram

    // warp inclusive scan
    int run = v;
#pragma unroll
    for (int ofs = 1; ofs < 32; ofs <<= 1) {
        int u = __shfl_up_sync(0xffffffffu, run, ofs);
        if (l >= ofs) run += u;
    }
    if (l == 31) swp[wid] = run;
    __syncthreads();
    if (wid == 0) {
        int wv = swp[l];
        int wrun = wv;
#pragma unroll
        for (int ofs = 1; ofs < 32; ofs <<= 1) {
            int u = __shfl_up_sync(0xffffffffu, wrun, ofs);
            if (l >= ofs) wrun += u;
        }
        swp[l] = wrun - wv;   // exclusive warp prefix
        if (l == 31) {
            g_bsum[b] = wrun;  // block total
            __threadfence();
            int arrived = atomicAdd(&g_cnt1, 1);
            if (arrived == nb - 1) {
                int acc = 0;
                for (int k = 0; k < nb; k++) { g_bpre[k] = acc; acc += g_bsum[k]; }
                g_off[n] = acc;
                __threadfence();
                g_flag1 = 1;
            }
        }
    }
    if (t == 0) { while (g_flag1 == 0) { __nanosleep(20); } }
    __syncthreads();
    __threadfence();
    int local_excl = run - v + swp[wid];
    int bp = g_bpre[b];
    if (idx < n) {
        int o = local_excl + bp;
        g_off[idx] = o;
        g_cur[idx] = o;
    }
    __syncthreads();
    // global sync #2: all g_cur written before any scatter
    if (t == 0) {
        __threadfence();
        int done = atomicAdd(&g_cnt2, 1);
        if (done == nb - 1) { __threadfence(); g_flag2 = 1; }
        while (g_flag2 == 0) { __nanosleep(20); }
    }
    __syncthreads();
    __threadfence();
    int nthreads = nb * 1024;
    for (int e = b * 1024 + t; e < E; e += nthreads) {
        int src = ei[e];
        int dst = ei[E + e];
        int p = atomicAdd(&g_cur[dst], 1);
        g_csr[p] = src;
    }
    // reset barrier state for the next graph replay
    __syncthreads();
    if (t == 0) {
        __threadfence();
        int done = atomicAdd(&g_cnt3, 1);
        if (done == nb - 1) {
            g_cnt1 = 0; g_cnt2 = 0; g_cnt3 = 0; g_flag1 = 0; g_flag2 = 0;
        }
    }
}

// ---------------- K2: GAT (warp/node, shift-softmax, fp16 math, uint4 csr) + LN ---------
__global__ __launch_bounds__(256, 4) void gat_kernel(const float* __restrict__ att,
                                                     const float* __restrict__ gbias,
                                                     const float* __restrict__ arr,
                                                     const float* __restrict__ dep,
                                                     const float* __restrict__ hard,
                                                     const void* __restrict__ tptr, int n) {
    int warp = (blockIdx.x * blockDim.x + threadIdx.x) >> 5;
    if (warp >= n) return;
    int l = threadIdx.x & 31;
    int i = warp;
    int base = l * 8;          // lane's 8 slots in the 256-wide [head][dim] vector
    int dimb = (l & 7) * 8;    // lane's 8 dims in 0..63

    float tv = decode_t(tptr);
    float a = arr[i], d = dep[i], h = hard[i];
    float prog = (tv - a) / fmaxf(d - a, 1.0f);
    float atl  = ((d - tv) <= 1.0f) ? 1.0f : 0.0f;

    const __half2 c02 = __floats2half2_rn(0.2f, 0.2f);
    const __half2 hz  = __floats2half2_rn(0.f, 0.f);

    __half2 att2[4], xr2[4];
#pragma unroll
    for (int c = 0; c < 4; c++)
        att2[c] = __floats2half2_rn(att[base + 2 * c], att[base + 2 * c + 1]);
#pragma unroll
    for (int c = 0; c < 4; c++) {
        float e0 = prog * g_WR3[base + 2 * c] + h * g_WR3[CDIM + base + 2 * c]
                 + atl * g_WR3[2 * CDIM + base + 2 * c] + g_bR[base + 2 * c];
        float e1 = prog * g_WR3[base + 2 * c + 1] + h * g_WR3[CDIM + base + 2 * c + 1]
                 + atl * g_WR3[2 * CDIM + base + 2 * c + 1] + g_bR[base + 2 * c + 1];
        xr2[c] = __floats2half2_rn(e0, e1);
    }

    // self-loop edge: its score p is the softmax shift reference (weight = 1)
    float acc[8];
    float s = 1.0f;
    float p;
    {
        uint4 r = *(const uint4*)&g_xlh[i * CDIM + base];
        const __half2* y2 = (const __half2*)&r;
        __half2 qh = hz;
#pragma unroll
        for (int c = 0; c < 4; c++) {
            __half2 v = __hadd2(y2[c], xr2[c]);
            v = __hmax2(v, __hmul2(v, c02));
            qh = __hfma2(v, att2[c], qh);
        }
        qh = __hadd2(qh, shfl_xor_h2(qh, 1));
        qh = __hadd2(qh, shfl_xor_h2(qh, 2));
        qh = __hadd2(qh, shfl_xor_h2(qh, 4));
        p = __low2float(qh) + __high2float(qh);
#pragma unroll
        for (int c = 0; c < 4; c++) {
            float2 f = __half22float2(y2[c]);
            acc[2 * c] = f.x; acc[2 * c + 1] = f.y;
        }
    }

    int e0i = g_off[i], e1i = g_off[i + 1];
    int j = e0i;
    // peel to 16B alignment so csr batches use one LDG.128 (1 wavefront vs 4)
    int jal = (e0i + 3) & ~3;
    if (jal > e1i) jal = e1i;
    for (; j < jal; j++) {
        int src = g_csr[j];
        uint4 r = *(const uint4*)&g_xlh[src * CDIM + base];
        const __half2* y2 = (const __half2*)&r;
        __half2 qh = hz;
#pragma unroll
        for (int c = 0; c < 4; c++) {
            __half2 v = __hadd2(y2[c], xr2[c]);
            v = __hmax2(v, __hmul2(v, c02));
            qh = __hfma2(v, att2[c], qh);
        }
        qh = __hadd2(qh, shfl_xor_h2(qh, 1));
        qh = __hadd2(qh, shfl_xor_h2(qh, 2));
        qh = __hadd2(qh, shfl_xor_h2(qh, 4));
        float q = __low2float(qh) + __high2float(qh);
        float wv = __expf(q - p);
        s += wv;
#pragma unroll
        for (int c = 0; c < 4; c++) {
            float2 f = __half22float2(y2[c]);
            acc[2 * c]     += wv * f.x;
            acc[2 * c + 1] += wv * f.y;
        }
    }
    for (; j + 3 < e1i; j += 4) {
        uint4 sv = *(const uint4*)&g_csr[j];   // 4 edge srcs in one load
        int s0 = (int)sv.x, s1 = (int)sv.y, s2 = (int)sv.z, s3 = (int)sv.w;
        uint4 r0 = *(const uint4*)&g_xlh[s0 * CDIM + base];
        uint4 r1 = *(const uint4*)&g_xlh[s1 * CDIM + base];
        uint4 r2 = *(const uint4*)&g_xlh[s2 * CDIM + base];
        uint4 r3 = *(const uint4*)&g_xlh[s3 * CDIM + base];
        const __half2* y0 = (const __half2*)&r0;
        const __half2* y1 = (const __half2*)&r1;
        const __half2* y2 = (const __half2*)&r2;
        const __half2* y3 = (const __half2*)&r3;

        __half2 q0 = hz, q1 = hz, q2 = hz, q3 = hz;
#pragma unroll
        for (int c = 0; c < 4; c++) {
            __half2 v0 = __hadd2(y0[c], xr2[c]);
            __half2 v1 = __hadd2(y1[c], xr2[c]);
            __half2 v2 = __hadd2(y2[c], xr2[c]);
            __half2 v3 = __hadd2(y3[c], xr2[c]);
            v0 = __hmax2(v0, __hmul2(v0, c02));
            v1 = __hmax2(v1, __hmul2(v1, c02));
            v2 = __hmax2(v2, __hmul2(v2, c02));
            v3 = __hmax2(v3, __hmul2(v3, c02));
            q0 = __hfma2(v0, att2[c], q0);
            q1 = __hfma2(v1, att2[c], q1);
            q2 = __hfma2(v2, att2[c], q2);
            q3 = __hfma2(v3, att2[c], q3);
        }
        // pack 2 edges per half2 word, reduce across the 8-lane head group
        __half2 A = __halves2half2(__hadd(__low2half(q0), __high2half(q0)),
                                   __hadd(__low2half(q1), __high2half(q1)));
        __half2 B = __halves2half2(__hadd(__low2half(q2), __high2half(q2)),
                                   __hadd(__low2half(q3), __high2half(q3)));
        A = __hadd2(A, shfl_xor_h2(A, 1));
        B = __hadd2(B, shfl_xor_h2(B, 1));
        A = __hadd2(A, shfl_xor_h2(A, 2));
        B = __hadd2(B, shfl_xor_h2(B, 2));
        A = __hadd2(A, shfl_xor_h2(A, 4));
        B = __hadd2(B, shfl_xor_h2(B, 4));

        float w0 = __expf(__low2float(A) - p);
        float w1 = __expf(__high2float(A) - p);
        float w2 = __expf(__low2float(B) - p);
        float w3 = __expf(__high2float(B) - p);
        s += w0 + w1 + w2 + w3;
#pragma unroll
        for (int c = 0; c < 4; c++) {
            float2 f0 = __half22float2(y0[c]);
            float2 f1 = __half22float2(y1[c]);
            float2 f2 = __half22float2(y2[c]);
            float2 f3 = __half22float2(y3[c]);
            acc[2 * c]     += w0 * f0.x + w1 * f1.x + w2 * f2.x + w3 * f3.x;
            acc[2 * c + 1] += w0 * f0.y + w1 * f1.y + w2 * f2.y + w3 * f3.y;
        }
    }
    for (; j < e1i; j++) {
        int src = g_csr[j];
        uint4 r = *(const uint4*)&g_xlh[src * CDIM + base];
        const __half2* y2 = (const __half2*)&r;
        __half2 qh = hz;
#pragma unroll
        for (int c = 0; c < 4; c++) {
            __half2 v = __hadd2(y2[c], xr2[c]);
            v = __hmax2(v, __hmul2(v, c02));
            qh = __hfma2(v, att2[c], qh);
        }
        qh = __hadd2(qh, shfl_xor_h2(qh, 1));
        qh = __hadd2(qh, shfl_xor_h2(qh, 2));
        qh = __hadd2(qh, shfl_xor_h2(qh, 4));
        float q = __low2float(qh) + __high2float(qh);
        float wv = __expf(q - p);
        s += wv;
#pragma unroll
        for (int c = 0; c < 4; c++) {
            float2 f = __half22float2(y2[c]);
            acc[2 * c]     += wv * f.x;
            acc[2 * c + 1] += wv * f.y;
        }
    }

    float inv = 1.0f / s;
#pragma unroll
    for (int u = 0; u < 8; u++) acc[u] *= inv;

    // sum across the 4 heads (lanes l, l^8, l^16, l^24 hold the same dims)
#pragma unroll
    for (int u = 0; u < 8; u++) {
        float v = acc[u];
        v += __shfl_xor_sync(0xffffffffu, v, 8);
        v += __shfl_xor_sync(0xffffffffu, v, 16);
        acc[u] = v;
    }

    // residual x recomputed from features + LN
    float xv[8];
    float sm = 0.f;
#pragma unroll
    for (int u = 0; u < 8; u++) {
        float x8 = prog * g_wc[dimb + u] + h * g_wc[HID + dimb + u]
                 + atl * g_wc[2 * HID + dimb + u] + g_bc[dimb + u];
        xv[u] = x8 + 0.25f * acc[u] + gbias[dimb + u];
        sm += xv[u];
    }
    sm += __shfl_xor_sync(0xffffffffu, sm, 1);
    sm += __shfl_xor_sync(0xffffffffu, sm, 2);
    sm += __shfl_xor_sync(0xffffffffu, sm, 4);
    float mu = sm * (1.0f / 64.0f);
    float sq = 0.f;
#pragma unroll
    for (int u = 0; u < 8; u++) { float dd = xv[u] - mu; sq += dd * dd; }
    sq += __shfl_xor_sync(0xffffffffu, sq, 1);
    sq += __shfl_xor_sync(0xffffffffu, sq, 2);
    sq += __shfl_xor_sync(0xffffffffu, sq, 4);
    float rs = rsqrtf(sq * (1.0f / 64.0f) + 1e-5f);

    if (l < 8) {
        float o[8];
#pragma unroll
        for (int u = 0; u < 8; u++) o[u] = (xv[u] - mu) * rs;
        *(float4*)&g_y[i * HID + dimb]     = make_float4(o[0], o[1], o[2], o[3]);
        *(float4*)&g_y[i * HID + dimb + 4] = make_float4(o[4], o[5], o[6], o[7]);
    }
}

// ---------------- K3: two residual ReLU FF layers (R10 4x4 config) ----------------
__global__ __launch_bounds__(256) void ff_kernel(const float* __restrict__ w1,
                                                 const float* __restrict__ b1,
                                                 const float* __restrict__ w2,
                                                 const float* __restrict__ b2,
                                                 float* __restrict__ out, int n) {
    __shared__ float ysT[64 * 68];
    __shared__ float ws [64 * 68];
    __shared__ float bsh[2 * 64];
    int tid = threadIdx.x;
    int n0  = blockIdx.x * 64;

#pragma unroll
    for (int i = 0; i < 4; i++) {
        int idx = tid + i * 256;
        int r   = idx >> 4;
        int c4  = (idx & 15) * 4;
        float4 v = make_float4(0.f, 0.f, 0.f, 0.f);
        if (n0 + r < n) v = *(const float4*)&g_y[(n0 + r) * HID + c4];
        ysT[(c4 + 0) * 68 + r] = v.x;
        ysT[(c4 + 1) * 68 + r] = v.y;
        ysT[(c4 + 2) * 68 + r] = v.z;
        ysT[(c4 + 3) * 68 + r] = v.w;
        *(float4*)&ws[r * 68 + c4] = *(const float4*)&w1[r * HID + c4];
    }
    if (tid < 64) { bsh[tid] = b1[tid]; bsh[64 + tid] = b2[tid]; }
    __syncthreads();

    int tn = (tid & 15) * 4;
    int tc = (tid >> 4) * 4;

    float z[4][4];
    {
        float acc[4][4];
#pragma unroll
        for (int aa = 0; aa < 4; aa++)
#pragma unroll
            for (int bb = 0; bb < 4; bb++) acc[aa][bb] = 0.f;
#pragma unroll 16
        for (int k = 0; k < 64; k++) {
            float4 av = *(const float4*)&ysT[k * 68 + tn];
            float4 bv = *(const float4*)&ws [k * 68 + tc];
            float a4[4] = {av.x, av.y, av.z, av.w};
            float b4[4] = {bv.x, bv.y, bv.z, bv.w};
#pragma unroll
            for (int ii = 0; ii < 4; ii++)
#pragma unroll
                for (int jj = 0; jj < 4; jj++) acc[ii][jj] += a4[ii] * b4[jj];
        }
#pragma unroll
        for (int nn = 0; nn < 4; nn++)
#pragma unroll
            for (int cc = 0; cc < 4; cc++) {
                float yv = ysT[(tc + cc) * 68 + tn + nn];
                float r  = acc[nn][cc] + bsh[tc + cc];
                z[nn][cc] = yv + fmaxf(r, 0.f);
            }
    }
    __syncthreads();

#pragma unroll
    for (int cc = 0; cc < 4; cc++)
        *(float4*)&ysT[(tc + cc) * 68 + tn] =
            make_float4(z[0][cc], z[1][cc], z[2][cc], z[3][cc]);
#pragma unroll
    for (int i = 0; i < 4; i++) {
        int idx = tid + i * 256;
        int r   = idx >> 4;
        int c4  = (idx & 15) * 4;
        *(float4*)&ws[r * 68 + c4] = *(const float4*)&w2[r * HID + c4];
    }
    __syncthreads();

    float acc2[4][4];
#pragma unroll
    for (int aa = 0; aa < 4; aa++)
#pragma unroll
        for (int bb = 0; bb < 4; bb++) acc2[aa][bb] = 0.f;
#pragma unroll 16
    for (int k = 0; k < 64; k++) {
        float4 av = *(const float4*)&ysT[k * 68 + tn];
        float4 bv = *(const float4*)&ws [k * 68 + tc];
        float a4[4] = {av.x, av.y, av.z, av.w};
        float b4[4] = {bv.x, bv.y, bv.z, bv.w};
#pragma unroll
        for (int ii = 0; ii < 4; ii++)
#pragma unroll
            for (int jj = 0; jj < 4; jj++) acc2[ii][jj] += a4[ii] * b4[jj];
    }
#pragma unroll
    for (int nn = 0; nn < 4; nn++) {
        int row = n0 + tn + nn;
        if (row < n) {
            float o[4];
#pragma unroll
            for (int cc = 0; cc < 4; cc++) {
                float zv = ysT[(tc + cc) * 68 + tn + nn];
                float r2 = acc2[nn][cc] + bsh[64 + tc + cc];
                o[cc] = zv + fmaxf(r2, 0.f);
            }
            *(float4*)&out[row * HID + tc] = make_float4(o[0], o[1], o[2], o[3]);
        }
    }
}

// ---------------- launch ----------------
extern "C" void kernel_launch(void* const* d_in, const int* in_sizes, int n_in,
                              void* d_out, int out_size) {
    const float* arrivals = (const float*)d_in[0];
    const float* departs  = (const float*)d_in[1];
    const float* hard     = (const float*)d_in[2];
    const float* w_emb1   = (const float*)d_in[3];
    const float* b_emb1   = (const float*)d_in[4];
    const float* w_emb2   = (const float*)d_in[5];
    const float* b_emb2   = (const float*)d_in[6];
    const float* gat_wl   = (const float*)d_in[7];
    const float* gat_wr   = (const float*)d_in[8];
    const float* gat_att  = (const float*)d_in[9];
    const float* gat_bias = (const float*)d_in[10];
    const float* w_ff1    = (const float*)d_in[11];
    const float* b_ff1    = (const float*)d_in[12];
    const float* w_ff2    = (const float*)d_in[13];
    const float* b_ff2    = (const float*)d_in[14];
    const int*   edge     = (const int*)d_in[15];
    const void*  tptr     = d_in[16];

    int n = in_sizes[0];
    int E = in_sizes[15] / 2;

    xlprep_kernel<<<296, 256>>>(arrivals, departs, hard, tptr,
                                w_emb1, b_emb1, w_emb2, b_emb2,
                                gat_wl, gat_wr, edge, n, E);                        // 0
    int nb = (n + 1023) / 1024;
    scan_scatter_kernel<<<nb, 1024>>>(edge, n, E);                                  // 1
    gat_kernel<<<(n + 7) / 8, 256>>>(gat_att, gat_bias, arrivals, departs, hard,
                                     tptr, n);                                      // 2
    ff_kernel<<<(n + 63) / 64, 256>>>(w_ff1, b_ff1, w_ff2, b_ff2, (float*)d_out, n); // 3
}

// round 15
// speedup vs baseline: 1.3976x; 1.0335x over previous
#include <cuda_runtime.h>
#include <cuda_fp16.h>

#define HID   64
#define CDIM  256     // HEADS*HID
#define NMAX  65536
#define EMAX  524288

// ---------------- scratch (static device arrays; no allocation) ----------------
__device__ float  g_wc [3 * HID];         // combined embedding weight [3][64]
__device__ float  g_bc [HID];             // combined embedding bias
__device__ float  g_WR3[3 * CDIM];        // Wc @ gat_wr  [3][256]
__device__ float  g_bR [CDIM];
__device__ __half g_xlh[NMAX * CDIM];     // x @ gat_wl  in fp16 (gather operand)
__device__ float  g_y [NMAX * HID];       // post-LN features
__device__ int    g_deg [NMAX];           // zeroed by scan_scatter each replay
__device__ int    g_off [NMAX + 1];
__device__ int    g_cur [NMAX];
__device__ int    g_bsum[64];
__device__ int    g_bpre[64];
__device__ int    g_cnt1 = 0;
__device__ int    g_cnt2 = 0;
__device__ int    g_cnt3 = 0;
__device__ volatile int g_flag1 = 0;
__device__ volatile int g_flag2 = 0;
__device__ int    g_csr [EMAX];           // src per dst-sorted edge

// ---------------- helpers ----------------
__device__ __forceinline__ float decode_t(const void* p) {
    int iv = *(const int*)p;
    if (iv > -16777216 && iv < 16777216) return (float)iv;   // int32 / int64 low word
    return __int_as_float(iv);                               // float32
}

__device__ __forceinline__ __half2 shfl_xor_h2(__half2 v, int m) {
    unsigned u = *(unsigned*)&v;
    u = __shfl_xor_sync(0xffffffffu, u, m);
    return *(__half2*)&u;
}

// ---------------- K0: fused prep + xl(fp16) + dst histogram (persistent) ----------------
__global__ __launch_bounds__(256) void xlprep_kernel(
        const float* __restrict__ arr, const float* __restrict__ dep,
        const float* __restrict__ hard, const void* __restrict__ tptr,
        const float* __restrict__ w1, const float* __restrict__ b1,
        const float* __restrict__ w2, const float* __restrict__ b2,
        const float* __restrict__ wl, const float* __restrict__ wr,
        const int* __restrict__ ei, int n, int E) {
    __shared__ float sWc[3 * HID];
    __shared__ float sbc[HID];
    __shared__ float sWL[3 * CDIM];
    __shared__ float sbL[CDIM];
    int t = threadIdx.x;   // 256 threads

    if (t < HID) {
        float c0 = 0.f, c1 = 0.f, c2 = 0.f, cb = 0.f;
        for (int k = 0; k < HID; k++) {
            float wkj = w2[k * HID + t];
            c0 += w1[k] * wkj;
            c1 += w1[HID + k] * wkj;
            c2 += w1[2 * HID + k] * wkj;
            cb += b1[k] * wkj;
        }
        sWc[t] = c0; sWc[HID + t] = c1; sWc[2 * HID + t] = c2; sbc[t] = cb + b2[t];
    }
    __syncthreads();

    {   // WL3 columns (all blocks; needed locally)
        float l0 = 0.f, l1 = 0.f, l2 = 0.f, lb = 0.f;
#pragma unroll 8
        for (int j = 0; j < HID; j++) {
            float wlv = wl[j * CDIM + t];
            l0 += sWc[j] * wlv;
            l1 += sWc[HID + j] * wlv;
            l2 += sWc[2 * HID + j] * wlv;
            lb += sbc[j] * wlv;
        }
        sWL[t] = l0; sWL[CDIM + t] = l1; sWL[2 * CDIM + t] = l2; sbL[t] = lb;
    }
    if (blockIdx.x == 0) {   // WR3 + wc/bc to global (only gat needs them)
        float r0 = 0.f, r1 = 0.f, r2 = 0.f, rb = 0.f;
#pragma unroll 8
        for (int j = 0; j < HID; j++) {
            float wrv = wr[j * CDIM + t];
            r0 += sWc[j] * wrv;
            r1 += sWc[HID + j] * wrv;
            r2 += sWc[2 * HID + j] * wrv;
            rb += sbc[j] * wrv;
        }
        g_WR3[t] = r0; g_WR3[CDIM + t] = r1; g_WR3[2 * CDIM + t] = r2; g_bR[t] = rb;
        if (t < HID) {
            g_wc[t] = sWc[t]; g_wc[HID + t] = sWc[HID + t];
            g_wc[2 * HID + t] = sWc[2 * HID + t]; g_bc[t] = sbc[t];
        }
    }
    __syncthreads();

    float tv = decode_t(tptr);
    int total = n * 32;
    for (int idx = blockIdx.x * 256 + t; idx < total; idx += gridDim.x * 256) {
        int node = idx >> 5;
        int c = (idx & 31) * 8;
        float a = arr[node], d = dep[node], h = hard[node];
        float prog = (tv - a) / fmaxf(d - a, 1.0f);
        float atl  = ((d - tv) <= 1.0f) ? 1.0f : 0.0f;

        float o[8];
#pragma unroll
        for (int u = 0; u < 8; u++)
            o[u] = prog * sWL[c + u] + h * sWL[CDIM + c + u]
                 + atl * sWL[2 * CDIM + c + u] + sbL[c + u];

        uint4 pk;
        ((__half2*)&pk.x)[0] = __floats2half2_rn(o[0], o[1]);
        ((__half2*)&pk.x)[1] = __floats2half2_rn(o[2], o[3]);
        ((__half2*)&pk.z)[0] = __floats2half2_rn(o[4], o[5]);
        ((__half2*)&pk.z)[1] = __floats2half2_rn(o[6], o[7]);
        *(uint4*)&g_xlh[node * CDIM + c] = pk;
    }

    // destination histogram (g_deg zeroed by previous replay's scan_scatter)
    for (int e = blockIdx.x * 256 + t; e < E; e += gridDim.x * 256)
        atomicAdd(&g_deg[ei[E + e]], 1);
}

// ---------------- K1: fused scan + scatter (grid-wide sync via counters) ----------------
__global__ __launch_bounds__(1024) void scan_scatter_kernel(const int* __restrict__ ei,
                                                            int n, int E) {
    __shared__ int swp[32];   // per-warp totals / exclusive prefixes
    int t = threadIdx.x;
    int b = blockIdx.x;
    int nb = gridDim.x;
    int wid = t >> 5;
    int l = t & 31;
    int idx = b * 1024 + t;
    int v = (idx < n) ? g_deg[idx] : 0;
    if (idx < n) g_deg[idx] = 0;          // reset for next replay's histogram

    // warp inclusive scan
    int run = v;
#pragma unroll
    for (int ofs = 1; ofs < 32; ofs <<= 1) {
        int u = __shfl_up_sync(0xffffffffu, run, ofs);
        if (l >= ofs) run += u;
    }
    if (l == 31) swp[wid] = run;
    __syncthreads();
    if (wid == 0) {
        int wv = swp[l];
        int wrun = wv;
#pragma unroll
        for (int ofs = 1; ofs < 32; ofs <<= 1) {
            int u = __shfl_up_sync(0xffffffffu, wrun, ofs);
            if (l >= ofs) wrun += u;
        }
        swp[l] = wrun - wv;   // exclusive warp prefix
        if (l == 31) {
            g_bsum[b] = wrun;  // block total
            __threadfence();
            int arrived = atomicAdd(&g_cnt1, 1);
            if (arrived == nb - 1) {
                int acc = 0;
                for (int k = 0; k < nb; k++) { g_bpre[k] = acc; acc += g_bsum[k]; }
                g_off[n] = acc;
                __threadfence();
                g_flag1 = 1;
            }
        }
    }
    if (t == 0) { while (g_flag1 == 0) { __nanosleep(20); } }
    __syncthreads();
    __threadfence();
    int local_excl = run - v + swp[wid];
    int bp = g_bpre[b];
    if (idx < n) {
        int o = local_excl + bp;
        g_off[idx] = o;
        g_cur[idx] = o;
    }
    __syncthreads();
    // global sync #2: all g_cur written before any scatter
    if (t == 0) {
        __threadfence();
        int done = atomicAdd(&g_cnt2, 1);
        if (done == nb - 1) { __threadfence(); g_flag2 = 1; }
        while (g_flag2 == 0) { __nanosleep(20); }
    }
    __syncthreads();
    __threadfence();
    int nthreads = nb * 1024;
    for (int e = b * 1024 + t; e < E; e += nthreads) {
        int src = ei[e];
        int dst = ei[E + e];
        int p = atomicAdd(&g_cur[dst], 1);
        g_csr[p] = src;
    }
    // reset barrier state for the next graph replay
    __syncthreads();
    if (t == 0) {
        __threadfence();
        int done = atomicAdd(&g_cnt3, 1);
        if (done == nb - 1) {
            g_cnt1 = 0; g_cnt2 = 0; g_cnt3 = 0; g_flag1 = 0; g_flag2 = 0;
        }
    }
}

// ---------------- K2: GAT (warp/node, shift-softmax, fp16 math + fp16 acc) + LN ---------
__global__ __launch_bounds__(256, 4) void gat_kernel(const float* __restrict__ att,
                                                     const float* __restrict__ gbias,
                                                     const float* __restrict__ arr,
                                                     const float* __restrict__ dep,
                                                     const float* __restrict__ hard,
                                                     const void* __restrict__ tptr, int n) {
    int warp = (blockIdx.x * blockDim.x + threadIdx.x) >> 5;
    if (warp >= n) return;
    int l = threadIdx.x & 31;
    int i = warp;
    int base = l * 8;          // lane's 8 slots in the 256-wide [head][dim] vector
    int dimb = (l & 7) * 8;    // lane's 8 dims in 0..63

    float tv = decode_t(tptr);
    float a = arr[i], d = dep[i], h = hard[i];
    float prog = (tv - a) / fmaxf(d - a, 1.0f);
    float atl  = ((d - tv) <= 1.0f) ? 1.0f : 0.0f;

    const __half2 c02 = __floats2half2_rn(0.2f, 0.2f);
    const __half2 hz  = __floats2half2_rn(0.f, 0.f);

    __half2 att2[4], xr2[4];
#pragma unroll
    for (int c = 0; c < 4; c++)
        att2[c] = __floats2half2_rn(att[base + 2 * c], att[base + 2 * c + 1]);
#pragma unroll
    for (int c = 0; c < 4; c++) {
        float e0 = prog * g_WR3[base + 2 * c] + h * g_WR3[CDIM + base + 2 * c]
                 + atl * g_WR3[2 * CDIM + base + 2 * c] + g_bR[base + 2 * c];
        float e1 = prog * g_WR3[base + 2 * c + 1] + h * g_WR3[CDIM + base + 2 * c + 1]
                 + atl * g_WR3[2 * CDIM + base + 2 * c + 1] + g_bR[base + 2 * c + 1];
        xr2[c] = __floats2half2_rn(e0, e1);
    }

    // self-loop edge: its score p is the softmax shift reference (weight = 1)
    __half2 acch[4];           // fp16x2 accumulator (lane's 8 slots)
    float s = 1.0f;
    float p;
    {
        uint4 r = *(const uint4*)&g_xlh[i * CDIM + base];
        const __half2* y2 = (const __half2*)&r;
        __half2 qh = hz;
#pragma unroll
        for (int c = 0; c < 4; c++) {
            __half2 v = __hadd2(y2[c], xr2[c]);
            v = __hmax2(v, __hmul2(v, c02));
            qh = __hfma2(v, att2[c], qh);
        }
        qh = __hadd2(qh, shfl_xor_h2(qh, 1));
        qh = __hadd2(qh, shfl_xor_h2(qh, 2));
        qh = __hadd2(qh, shfl_xor_h2(qh, 4));
        p = __low2float(qh) + __high2float(qh);
#pragma unroll
        for (int c = 0; c < 4; c++) acch[c] = y2[c];
    }

    int e0i = g_off[i], e1i = g_off[i + 1];
    int j = e0i;
    for (; j + 3 < e1i; j += 4) {
        int s0 = g_csr[j], s1 = g_csr[j + 1], s2 = g_csr[j + 2], s3 = g_csr[j + 3];
        uint4 r0 = *(const uint4*)&g_xlh[s0 * CDIM + base];
        uint4 r1 = *(const uint4*)&g_xlh[s1 * CDIM + base];
        uint4 r2 = *(const uint4*)&g_xlh[s2 * CDIM + base];
        uint4 r3 = *(const uint4*)&g_xlh[s3 * CDIM + base];
        const __half2* y0 = (const __half2*)&r0;
        const __half2* y1 = (const __half2*)&r1;
        const __half2* y2 = (const __half2*)&r2;
        const __half2* y3 = (const __half2*)&r3;

        __half2 q0 = hz, q1 = hz, q2 = hz, q3 = hz;
#pragma unroll
        for (int c = 0; c < 4; c++) {
            __half2 v0 = __hadd2(y0[c], xr2[c]);
            __half2 v1 = __hadd2(y1[c], xr2[c]);
            __half2 v2 = __hadd2(y2[c], xr2[c]);
            __half2 v3 = __hadd2(y3[c], xr2[c]);
            v0 = __hmax2(v0, __hmul2(v0, c02));
            v1 = __hmax2(v1, __hmul2(v1, c02));
            v2 = __hmax2(v2, __hmul2(v2, c02));
            v3 = __hmax2(v3, __hmul2(v3, c02));
            q0 = __hfma2(v0, att2[c], q0);
            q1 = __hfma2(v1, att2[c], q1);
            q2 = __hfma2(v2, att2[c], q2);
            q3 = __hfma2(v3, att2[c], q3);
        }
        // pack 2 edges per half2 word, reduce across the 8-lane head group
        __half2 A = __halves2half2(__hadd(__low2half(q0), __high2half(q0)),
                                   __hadd(__low2half(q1), __high2half(q1)));
        __half2 B = __halves2half2(__hadd(__low2half(q2), __high2half(q2)),
                                   __hadd(__low2half(q3), __high2half(q3)));
        A = __hadd2(A, shfl_xor_h2(A, 1));
        B = __hadd2(B, shfl_xor_h2(B, 1));
        A = __hadd2(A, shfl_xor_h2(A, 2));
        B = __hadd2(B, shfl_xor_h2(B, 2));
        A = __hadd2(A, shfl_xor_h2(A, 4));
        B = __hadd2(B, shfl_xor_h2(B, 4));

        float w0 = __expf(__low2float(A) - p);
        float w1 = __expf(__high2float(A) - p);
        float w2 = __expf(__low2float(B) - p);
        float w3 = __expf(__high2float(B) - p);
        s += w0 + w1 + w2 + w3;
        __half2 wh0 = __float2half2_rn(w0);
        __half2 wh1 = __float2half2_rn(w1);
        __half2 wh2 = __float2half2_rn(w2);
        __half2 wh3 = __float2half2_rn(w3);
#pragma unroll
        for (int c = 0; c < 4; c++) {
            acch[c] = __hfma2(wh0, y0[c], acch[c]);
            acch[c] = __hfma2(wh1, y1[c], acch[c]);
            acch[c] = __hfma2(wh2, y2[c], acch[c]);
            acch[c] = __hfma2(wh3, y3[c], acch[c]);
        }
    }
    for (; j < e1i; j++) {
        int src = g_csr[j];
        uint4 r = *(const uint4*)&g_xlh[src * CDIM + base];
        const __half2* y2 = (const __half2*)&r;
        __half2 qh = hz;
#pragma unroll
        for (int c = 0; c < 4; c++) {
            __half2 v = __hadd2(y2[c], xr2[c]);
            v = __hmax2(v, __hmul2(v, c02));
            qh = __hfma2(v, att2[c], qh);
        }
        qh = __hadd2(qh, shfl_xor_h2(qh, 1));
        qh = __hadd2(qh, shfl_xor_h2(qh, 2));
        qh = __hadd2(qh, shfl_xor_h2(qh, 4));
        float q = __low2float(qh) + __high2float(qh);
        float wv = __expf(q - p);
        s += wv;
        __half2 wh = __float2half2_rn(wv);
#pragma unroll
        for (int c = 0; c < 4; c++) acch[c] = __hfma2(wh, y2[c], acch[c]);
    }

    // normalize (fp32) and sum across the 4 heads (lanes l, l^8, l^16, l^24)
    float inv = 1.0f / s;
    float acc[8];
#pragma unroll
    for (int c = 0; c < 4; c++) {
        float2 f = __half22float2(acch[c]);
        acc[2 * c]     = f.x * inv;
        acc[2 * c + 1] = f.y * inv;
    }
#pragma unroll
    for (int u = 0; u < 8; u++) {
        float v = acc[u];
        v += __shfl_xor_sync(0xffffffffu, v, 8);
        v += __shfl_xor_sync(0xffffffffu, v, 16);
        acc[u] = v;
    }

    // residual x recomputed from features + LN
    float xv[8];
    float sm = 0.f;
#pragma unroll
    for (int u = 0; u < 8; u++) {
        float x8 = prog * g_wc[dimb + u] + h * g_wc[HID + dimb + u]
                 + atl * g_wc[2 * HID + dimb + u] + g_bc[dimb + u];
        xv[u] = x8 + 0.25f * acc[u] + gbias[dimb + u];
        sm += xv[u];
    }
    sm += __shfl_xor_sync(0xffffffffu, sm, 1);
    sm += __shfl_xor_sync(0xffffffffu, sm, 2);
    sm += __shfl_xor_sync(0xffffffffu, sm, 4);
    float mu = sm * (1.0f / 64.0f);
    float sq = 0.f;
#pragma unroll
    for (int u = 0; u < 8; u++) { float dd = xv[u] - mu; sq += dd * dd; }
    sq += __shfl_xor_sync(0xffffffffu, sq, 1);
    sq += __shfl_xor_sync(0xffffffffu, sq, 2);
    sq += __shfl_xor_sync(0xffffffffu, sq, 4);
    float rs = rsqrtf(sq * (1.0f / 64.0f) + 1e-5f);

    if (l < 8) {
        float o[8];
#pragma unroll
        for (int u = 0; u < 8; u++) o[u] = (xv[u] - mu) * rs;
        *(float4*)&g_y[i * HID + dimb]     = make_float4(o[0], o[1], o[2], o[3]);
        *(float4*)&g_y[i * HID + dimb + 4] = make_float4(o[4], o[5], o[6], o[7]);
    }
}

// ---------------- K3: two residual ReLU FF layers (R10 4x4 config) ----------------
__global__ __launch_bounds__(256) void ff_kernel(const float* __restrict__ w1,
                                                 const float* __restrict__ b1,
                                                 const float* __restrict__ w2,
                                                 const float* __restrict__ b2,
                                                 float* __restrict__ out, int n) {
    __shared__ float ysT[64 * 68];
    __shared__ float ws [64 * 68];
    __shared__ float bsh[2 * 64];
    int tid = threadIdx.x;
    int n0  = blockIdx.x * 64;

#pragma unroll
    for (int i = 0; i < 4; i++) {
        int idx = tid + i * 256;
        int r   = idx >> 4;
        int c4  = (idx & 15) * 4;
        float4 v = make_float4(0.f, 0.f, 0.f, 0.f);
        if (n0 + r < n) v = *(const float4*)&g_y[(n0 + r) * HID + c4];
        ysT[(c4 + 0) * 68 + r] = v.x;
        ysT[(c4 + 1) * 68 + r] = v.y;
        ysT[(c4 + 2) * 68 + r] = v.z;
        ysT[(c4 + 3) * 68 + r] = v.w;
        *(float4*)&ws[r * 68 + c4] = *(const float4*)&w1[r * HID + c4];
    }
    if (tid < 64) { bsh[tid] = b1[tid]; bsh[64 + tid] = b2[tid]; }
    __syncthreads();

    int tn = (tid & 15) * 4;
    int tc = (tid >> 4) * 4;

    float z[4][4];
    {
        float acc[4][4];
#pragma unroll
        for (int aa = 0; aa < 4; aa++)
#pragma unroll
            for (int bb = 0; bb < 4; bb++) acc[aa][bb] = 0.f;
#pragma unroll 16
        for (int k = 0; k < 64; k++) {
            float4 av = *(const float4*)&ysT[k * 68 + tn];
            float4 bv = *(const float4*)&ws [k * 68 + tc];
            float a4[4] = {av.x, av.y, av.z, av.w};
            float b4[4] = {bv.x, bv.y, bv.z, bv.w};
#pragma unroll
            for (int ii = 0; ii < 4; ii++)
#pragma unroll
                for (int jj = 0; jj < 4; jj++) acc[ii][jj] += a4[ii] * b4[jj];
        }
#pragma unroll
        for (int nn = 0; nn < 4; nn++)
#pragma unroll
            for (int cc = 0; cc < 4; cc++) {
                float yv = ysT[(tc + cc) * 68 + tn + nn];
                float r  = acc[nn][cc] + bsh[tc + cc];
                z[nn][cc] = yv + fmaxf(r, 0.f);
            }
    }
    __syncthreads();

#pragma unroll
    for (int cc = 0; cc < 4; cc++)
        *(float4*)&ysT[(tc + cc) * 68 + tn] =
            make_float4(z[0][cc], z[1][cc], z[2][cc], z[3][cc]);
#pragma unroll
    for (int i = 0; i < 4; i++) {
        int idx = tid + i * 256;
        int r   = idx >> 4;
        int c4  = (idx & 15) * 4;
        *(float4*)&ws[r * 68 + c4] = *(const float4*)&w2[r * HID + c4];
    }
    __syncthreads();

    float acc2[4][4];
#pragma unroll
    for (int aa = 0; aa < 4; aa++)
#pragma unroll
        for (int bb = 0; bb < 4; bb++) acc2[aa][bb] = 0.f;
#pragma unroll 16
    for (int k = 0; k < 64; k++) {
        float4 av = *(const float4*)&ysT[k * 68 + tn];
        float4 bv = *(const float4*)&ws [k * 68 + tc];
        float a4[4] = {av.x, av.y, av.z, av.w};
        float b4[4] = {bv.x, bv.y, bv.z, bv.w};
#pragma unroll
        for (int ii = 0; ii < 4; ii++)
#pragma unroll
            for (int jj = 0; jj < 4; jj++) acc2[ii][jj] += a4[ii] * b4[jj];
    }
#pragma unroll
    for (int nn = 0; nn < 4; nn++) {
        int row = n0 + tn + nn;
        if (row < n) {
            float o[4];
#pragma unroll
            for (int cc = 0; cc < 4; cc++) {
                float zv = ysT[(tc + cc) * 68 + tn + nn];
                float r2 = acc2[nn][cc] + bsh[64 + tc + cc];
                o[cc] = zv + fmaxf(r2, 0.f);
            }
            *(float4*)&out[row * HID + tc] = make_float4(o[0], o[1], o[2], o[3]);
        }
    }
}

// ---------------- launch ----------------
extern "C" void kernel_launch(void* const* d_in, const int* in_sizes, int n_in,
                              void* d_out, int out_size) {
    const float* arrivals = (const float*)d_in[0];
    const float* departs  = (const float*)d_in[1];
    const float* hard     = (const float*)d_in[2];
    const float* w_emb1   = (const float*)d_in[3];
    const float* b_emb1   = (const float*)d_in[4];
    const float* w_emb2   = (const float*)d_in[5];
    const float* b_emb2   = (const float*)d_in[6];
    const float* gat_wl   = (const float*)d_in[7];
    const float* gat_wr   = (const float*)d_in[8];
    const float* gat_att  = (const float*)d_in[9];
    const float* gat_bias = (const float*)d_in[10];
    const float* w_ff1    = (const float*)d_in[11];
    const float* b_ff1    = (const float*)d_in[12];
    const float* w_ff2    = (const float*)d_in[13];
    const float* b_ff2    = (const float*)d_in[14];
    const int*   edge     = (const int*)d_in[15];
    const void*  tptr     = d_in[16];

    int n = in_sizes[0];
    int E = in_sizes[15] / 2;

    xlprep_kernel<<<296, 256>>>(arrivals, departs, hard, tptr,
                                w_emb1, b_emb1, w_emb2, b_emb2,
                                gat_wl, gat_wr, edge, n, E);                        // 0
    int nb = (n + 1023) / 1024;
    scan_scatter_kernel<<<nb, 1024>>>(edge, n, E);                                  // 1
    gat_kernel<<<(n + 7) / 8, 256>>>(gat_att, gat_bias, arrivals, departs, hard,
                                     tptr, n);                                      // 2
    ff_kernel<<<(n + 63) / 64, 256>>>(w_ff1, b_ff1, w_ff2, b_ff2, (float*)d_out, n); // 3
}